// round 1
// baseline (speedup 1.0000x reference)
#include <cuda_runtime.h>

// PEPS 6x6, D=3, B=16. Boundary-vector contraction:
// state over horizontal cut: 6 column bonds (D^6) x horizontal bond h (D) = 3^7 = 2187.
// Per site: w'[spect, d, h'] = sum_{u,h} w[spect, u, h] * A[u,d,h,h'] (9 MACs/output).

#define LX 6
#define LY 6
#define NSITE 36
#define STATE 2187          // 3^7
#define NTHREADS 729        // 2187 / 3 outputs per thread

__global__ __launch_bounds__(NTHREADS, 1)
void peps_amplitude_kernel(const int* __restrict__ xcfg,
                           const float* __restrict__ T,
                           float* __restrict__ out) {
    __shared__ float S0[STATE];
    __shared__ float S1[STATE];
    __shared__ float At[NSITE * 81];   // spin-sliced site tensors A[u,d,l,r]
    __shared__ int   spins[NSITE];
    __shared__ int   sOff[NSITE];

    const int b   = blockIdx.x;
    const int tid = threadIdx.x;

    if (tid < NSITE) spins[tid] = xcfg[b * NSITE + tid];
    __syncthreads();

    if (tid < NSITE) {
        int xx = tid / LY, yy = tid % LY;
        int p  = spins[tid];
        int pu = (xx > 0)      ? spins[tid - LY] : 0;
        int pd = (xx < LX - 1) ? spins[tid + LY] : 0;
        int pl = (yy > 0)      ? spins[tid - 1]  : 0;
        int pr = (yy < LY - 1) ? spins[tid + 1]  : 0;
        sOff[tid] = (((p * 2 + pu) * 2 + pd) * 2 + pl) * 2 + pr;
    }
    // init state: delta at index 0 (all boundary bonds = 0)
    for (int i = tid; i < STATE; i += NTHREADS) S0[i] = (i == 0) ? 1.0f : 0.0f;
    __syncthreads();

    // Gather all 36 site tiles: T[(site)*2592 + (u*27+d*9+l*3+r)*32 + sOff]
    for (int i = tid; i < NSITE * 81; i += NTHREADS) {
        int t = i / 81, e = i - t * 81;
        At[i] = T[t * 2592 + e * 32 + sOff[t]];
    }
    __syncthreads();

    float* cur = S0;
    float* nxt = S1;

    // digit strides: index = c0*729 + c1*243 + c2*81 + c3*27 + c4*9 + c5*3 + h
    const int pw3[6] = {729, 243, 81, 27, 9, 3};

    #pragma unroll 1
    for (int xx = 0; xx < LX; ++xx) {
        if (xx > 0) {
            // between rows: keep r==0 of previous row == l==0 of new row
            for (int i = tid; i < STATE; i += NTHREADS)
                if (i % 3 != 0) cur[i] = 0.0f;
            __syncthreads();
        }
        #pragma unroll
        for (int yy = 0; yy < LY; ++yy) {
            const float* __restrict__ A = &At[(xx * LY + yy) * 81];
            const int stride = pw3[yy];

            #pragma unroll
            for (int k = 0; k < 3; ++k) {
                int i  = tid + k * NTHREADS;
                int hp = i % 3;
                int d  = (i / stride) % 3;
                int base = i - hp - d * stride;
                float acc = 0.0f;
                #pragma unroll
                for (int u = 0; u < 3; ++u) {
                    #pragma unroll
                    for (int h = 0; h < 3; ++h) {
                        acc = fmaf(cur[base + u * stride + h],
                                   A[u * 27 + d * 9 + h * 3 + hp], acc);
                    }
                }
                nxt[i] = acc;
            }
            __syncthreads();
            float* tmp = cur; cur = nxt; nxt = tmp;
        }
    }

    if (tid == 0) out[b] = cur[0];
}

extern "C" void kernel_launch(void* const* d_in, const int* in_sizes, int n_in,
                              void* d_out, int out_size) {
    // identify inputs by size: x is 16*36=576 int32, T is 93312 float32
    const int*   xcfg = nullptr;
    const float* T    = nullptr;
    for (int i = 0; i < n_in; ++i) {
        if (in_sizes[i] == 576)   xcfg = (const int*)d_in[i];
        else                      T    = (const float*)d_in[i];
    }
    float* out = (float*)d_out;
    peps_amplitude_kernel<<<16, NTHREADS>>>(xcfg, T, out);
}

// round 2
// speedup vs baseline: 1.6098x; 1.6098x over previous
#include <cuda_runtime.h>

// PEPS 6x6, D=3, B=16 — bidirectional boundary-vector contraction.
// amplitude = e0^T M0 M1 M2 M3 M4 M5 e0  (M_x = row transfer matrix, 729x729)
// Kernel 1 (32 CTAs): CTA (b,half) computes half-vector:
//   top    (half=0): t = e0^T M0 M1 M2   (rows 0,1,2 downward)
//   bottom (half=1): v = M3 M4 M5 e0     (rows 5,4,3 upward, u<->d swapped)
// Kernel 2 (16 CTAs): out[b] = dot(t, v) over 729.
//
// State: 729 groups (6 base-3 column-bond digits) x h (horizontal bond),
// padded to 4 floats/group for LDS.128/STS.128. Site tensors pre-gathered
// per spin config into SMEM as At[site][o][hp][u][4] (h in .x/.y/.z).

#define NT 729
#define SPAD 2916            // 729 groups * 4
#define ATF 108              // floats per padded site tensor (3*3*3*4)

__device__ float g_half[32 * 729];

__global__ __launch_bounds__(NT, 1)
void peps_half_kernel(const int* __restrict__ xcfg,
                      const float* __restrict__ T) {
    __shared__ float S0[SPAD];
    __shared__ float S1[SPAD];
    __shared__ float At[18 * ATF];     // 18 sites, processing order
    __shared__ int spins[36];
    __shared__ int sOff[36];

    const int t = threadIdx.x;
    const int b = blockIdx.x >> 1;
    const int bottom = blockIdx.x & 1;

    if (t < 36) spins[t] = xcfg[b * 36 + t];
    __syncthreads();
    if (t < 36) {
        int xx = t / 6, yy = t % 6;
        int p  = spins[t];
        int pu = (xx > 0) ? spins[t - 6] : 0;
        int pd = (xx < 5) ? spins[t + 6] : 0;
        int pl = (yy > 0) ? spins[t - 1] : 0;
        int pr = (yy < 5) ? spins[t + 1] : 0;
        sOff[t] = (((p * 2 + pu) * 2 + pd) * 2 + pl) * 2 + pr;
    }
    for (int i = t; i < SPAD; i += NT) S0[i] = 0.0f;
    __syncthreads();

    // Gather padded site tensors. Aeff[a(contracted), o(output), h, hp]:
    //   top:    = T site (s/6, s%6)      u=a, d=o
    //   bottom: = T site (5-s/6, s%6)    u=o, d=a
    for (int i = t; i < 18 * ATF; i += NT) {
        int s = i / ATF, r = i - s * ATF;
        int o = r / 36;  r -= o * 36;
        int hp = r / 12; r -= hp * 12;
        int a = r >> 2, h = r & 3;
        float v = 0.0f;
        if (h < 3) {
            int x = bottom ? 5 - s / 6 : s / 6;
            int y = s % 6;
            int u = bottom ? o : a;
            int d = bottom ? a : o;
            int site = x * 6 + y;
            v = T[site * 2592 + (((u * 3 + d) * 3 + h) * 3 + hp) * 32 + sOff[site]];
        }
        At[i] = v;
    }
    __syncthreads();

    // Init = state after first site (row-first, y=0): only digit c0=o, h=hp
    // nonzero: S0[4*(o*243)+hp] = Aeff[a=0, o, h=0, hp]  (site index 0 in At)
    if (t < 9) {
        int o = t / 3, hp = t - 3 * o;
        S0[(o * 243) * 4 + hp] = At[o * 36 + hp * 12];
    }
    __syncthreads();

    float* cur = S0;
    float* nxt = S1;
    const float4* Atv = (const float4*)At;

#define STEP(SITE, S3, TRANS) { \
    int o_  = (t / (S3)) % 3; \
    int b3_ = t - o_ * (S3); \
    const float4* C_ = (const float4*)cur; \
    float4 c0 = C_[b3_]; \
    float4 c1 = C_[b3_ + (S3)]; \
    float4 c2 = C_[b3_ + 2 * (S3)]; \
    const float4* Av = Atv + (SITE) * 27 + o_ * 9; \
    float r0, r1, r2; \
    if (TRANS) { \
        r0 = c0.x * Av[0].x + c1.x * Av[1].x + c2.x * Av[2].x; \
        r1 = c0.x * Av[3].x + c1.x * Av[4].x + c2.x * Av[5].x; \
        r2 = c0.x * Av[6].x + c1.x * Av[7].x + c2.x * Av[8].x; \
    } else { \
        float4 a0 = Av[0], a1 = Av[1], a2 = Av[2]; \
        r0 = c0.x*a0.x + c0.y*a0.y + c0.z*a0.z \
           + c1.x*a1.x + c1.y*a1.y + c1.z*a1.z \
           + c2.x*a2.x + c2.y*a2.y + c2.z*a2.z; \
        a0 = Av[3]; a1 = Av[4]; a2 = Av[5]; \
        r1 = c0.x*a0.x + c0.y*a0.y + c0.z*a0.z \
           + c1.x*a1.x + c1.y*a1.y + c1.z*a1.z \
           + c2.x*a2.x + c2.y*a2.y + c2.z*a2.z; \
        a0 = Av[6]; a1 = Av[7]; a2 = Av[8]; \
        r2 = c0.x*a0.x + c0.y*a0.y + c0.z*a0.z \
           + c1.x*a1.x + c1.y*a1.y + c1.z*a1.z \
           + c2.x*a2.x + c2.y*a2.y + c2.z*a2.z; \
    } \
    ((float4*)nxt)[t] = make_float4(r0, r1, r2, 0.0f); \
    __syncthreads(); \
    { float* tmp_ = cur; cur = nxt; nxt = tmp_; } \
}

    // digit strides (in group units 3^(5-y)): y: 0->243 1->81 2->27 3->9 4->3 5->1
    // row 0: sites 1..5 (site 0 folded into init)
    STEP(1, 81, false)
    STEP(2, 27, false)
    STEP(3, 9, false)
    STEP(4, 3, false)
    STEP(5, 1, false)
    // row 1: transition step at y=0 (projects prev h->0, new l=0)
    STEP(6, 243, true)
    STEP(7, 81, false)
    STEP(8, 27, false)
    STEP(9, 9, false)
    STEP(10, 3, false)
    STEP(11, 1, false)
    // row 2
    STEP(12, 243, true)
    STEP(13, 81, false)
    STEP(14, 27, false)
    STEP(15, 9, false)
    STEP(16, 3, false)
    STEP(17, 1, false)
#undef STEP

    // project final h -> 0 and write half-vector
    g_half[blockIdx.x * 729 + t] = cur[4 * t];
}

__global__ __launch_bounds__(128)
void peps_dot_kernel(float* __restrict__ out) {
    const int b = blockIdx.x, t = threadIdx.x;
    const float* a = g_half + (2 * b) * 729;
    const float* c = g_half + (2 * b + 1) * 729;
    float s = 0.0f;
    for (int g = t; g < 729; g += 128) s += a[g] * c[g];
    #pragma unroll
    for (int o = 16; o; o >>= 1) s += __shfl_xor_sync(0xFFFFFFFFu, s, o);
    __shared__ float red[4];
    if ((t & 31) == 0) red[t >> 5] = s;
    __syncthreads();
    if (t == 0) out[b] = red[0] + red[1] + red[2] + red[3];
}

extern "C" void kernel_launch(void* const* d_in, const int* in_sizes, int n_in,
                              void* d_out, int out_size) {
    const int*   xcfg = nullptr;
    const float* T    = nullptr;
    for (int i = 0; i < n_in; ++i) {
        if (in_sizes[i] == 576) xcfg = (const int*)d_in[i];
        else                    T    = (const float*)d_in[i];
    }
    float* out = (float*)d_out;
    peps_half_kernel<<<32, NT>>>(xcfg, T);
    peps_dot_kernel<<<16, 128>>>(out);
}

// round 3
// speedup vs baseline: 2.0000x; 1.2424x over previous
#include <cuda_runtime.h>
#include <cstdint>

// PEPS 6x6, D=3, B=16 — fused bidirectional contraction, one kernel.
// Cluster of 2 CTAs per config: rank0 = top half (rows 0-2), rank1 = bottom
// (rows 5-3, u<->d swapped). Each computes a 729-vector over the middle cut;
// rank1 pushes its vector into rank0's SMEM via DSMEM; rank0 dots and writes.
//
// 243 workers x 3 output groups: state float4/group (h in xyz), site tensors
// padded [o][hp][a][4] so every access is LDS.128 and A loads are warp-broadcast.

#define NT 256       // block size (8 full warps)
#define NW 243       // active workers in contraction steps
#define SPAD 2916    // 729 groups * 4 floats
#define ATF 108      // padded floats per site tensor (3*3*3*4)

__device__ __forceinline__ float dot3(float4 a, float4 b) {
    return a.x * b.x + a.y * b.y + a.z * b.z;
}

__device__ __forceinline__ uint32_t smem_u32(const void* p) {
    uint32_t a;
    asm("{ .reg .u64 t; cvta.to.shared.u64 t, %1; cvt.u32.u64 %0, t; }"
        : "=r"(a) : "l"(p));
    return a;
}

__device__ __forceinline__ void st_cluster_f32(uint32_t laddr, float v) {
    uint32_t r;
    asm volatile("mapa.shared::cluster.u32 %0, %1, 0;" : "=r"(r) : "r"(laddr));
    asm volatile("st.shared::cluster.f32 [%0], %1;" :: "r"(r), "f"(v) : "memory");
}

__global__ __launch_bounds__(NT, 1) __cluster_dims__(2, 1, 1)
void peps_fused_kernel(const int* __restrict__ xcfg,
                       const float* __restrict__ T,
                       float* __restrict__ out) {
    __shared__ float S0[SPAD];
    __shared__ float S1[SPAD];
    __shared__ float At[18 * ATF];
    __shared__ int   spins[36];
    __shared__ int   sOff[36];
    __shared__ float R[729];     // my projected half-vector
    __shared__ float P[729];     // peer's half-vector (rank0 only, DSMEM target)
    __shared__ float red[8];

    const int t = threadIdx.x;
    const int b = blockIdx.x >> 1;
    uint32_t rank;
    asm("mov.u32 %0, %%cluster_ctarank;" : "=r"(rank));
    const int bottom = (int)rank;

    if (t < 36) spins[t] = xcfg[b * 36 + t];
    __syncthreads();
    if (t < 36) {
        int xx = t / 6, yy = t % 6;
        int p  = spins[t];
        int pu = (xx > 0) ? spins[t - 6] : 0;
        int pd = (xx < 5) ? spins[t + 6] : 0;
        int pl = (yy > 0) ? spins[t - 1] : 0;
        int pr = (yy < 5) ? spins[t + 1] : 0;
        sOff[t] = (((p * 2 + pu) * 2 + pd) * 2 + pl) * 2 + pr;
    }
    for (int i = t; i < SPAD; i += NT) S0[i] = 0.0f;
    __syncthreads();

    // Gather padded site tensors Aeff[a(in), o(out), h, hp]:
    //   top:    T site (s/6, s%6),     u=a, d=o
    //   bottom: T site (5-s/6, s%6),   u=o, d=a
    for (int i = t; i < 18 * ATF; i += NT) {
        int s = i / ATF, r = i - s * ATF;
        int o  = r / 36;  r -= o * 36;
        int hp = r / 12;  r -= hp * 12;
        int a  = r >> 2,  h = r & 3;
        float v = 0.0f;
        if (h < 3) {
            int x = bottom ? 5 - s / 6 : s / 6;
            int y = s % 6;
            int u = bottom ? o : a;
            int d = bottom ? a : o;
            int site = x * 6 + y;
            v = T[site * 2592 + (((u * 3 + d) * 3 + h) * 3 + hp) * 32 + sOff[site]];
        }
        At[i] = v;
    }
    __syncthreads();

    // Init = state after first site (y=0): digit c0=o, h=hp
    if (t < 9) {
        int o = t / 3, hp = t - 3 * o;
        S0[(o * 243) * 4 + hp] = At[o * 36 + hp * 12];
    }
    __syncthreads();

    float* cur = S0;
    float* nxt = S1;

#define STEP(SITE, S3, TRANS) { \
    if (t < NW) { \
        int hi = t / (S3); \
        int lo = t - hi * (S3); \
        int base = hi * (3 * (S3)) + lo; \
        const float4* C_ = (const float4*)cur; \
        float4 c0 = C_[base]; \
        float4 c1 = C_[base + (S3)]; \
        float4 c2 = C_[base + 2 * (S3)]; \
        float4* N_ = (float4*)nxt; \
        _Pragma("unroll") \
        for (int o_ = 0; o_ < 3; ++o_) { \
            const float4* Av = (const float4*)At + (SITE) * 27 + o_ * 9; \
            float r0, r1, r2; \
            if (TRANS) { \
                r0 = c0.x * Av[0].x + c1.x * Av[1].x + c2.x * Av[2].x; \
                r1 = c0.x * Av[3].x + c1.x * Av[4].x + c2.x * Av[5].x; \
                r2 = c0.x * Av[6].x + c1.x * Av[7].x + c2.x * Av[8].x; \
            } else { \
                r0 = dot3(c0, Av[0]) + dot3(c1, Av[1]) + dot3(c2, Av[2]); \
                r1 = dot3(c0, Av[3]) + dot3(c1, Av[4]) + dot3(c2, Av[5]); \
                r2 = dot3(c0, Av[6]) + dot3(c1, Av[7]) + dot3(c2, Av[8]); \
            } \
            N_[base + o_ * (S3)] = make_float4(r0, r1, r2, 0.0f); \
        } \
    } \
    __syncthreads(); \
    { float* tmp_ = cur; cur = nxt; nxt = tmp_; } \
}

    // row 0 (site 0 folded into init): strides 3^(5-y)
    STEP(1, 81, false)
    STEP(2, 27, false)
    STEP(3, 9, false)
    STEP(4, 3, false)
    STEP(5, 1, false)
    // row 1 (transition at y=0 projects prev h -> 0, new l = 0)
    STEP(6, 243, true)
    STEP(7, 81, false)
    STEP(8, 27, false)
    STEP(9, 9, false)
    STEP(10, 3, false)
    STEP(11, 1, false)
    // row 2
    STEP(12, 243, true)
    STEP(13, 81, false)
    STEP(14, 27, false)
    STEP(15, 9, false)
    STEP(16, 3, false)
    STEP(17, 1, false)
#undef STEP

    // project h -> 0 into R
    for (int g = t; g < 729; g += NT) R[g] = cur[4 * g];
    __syncthreads();

    // rank1 pushes R into rank0's P via DSMEM
    if (bottom) {
        uint32_t pbase = smem_u32(P);
        for (int g = t; g < 729; g += NT)
            st_cluster_f32(pbase + g * 4, R[g]);
    }
    asm volatile("barrier.cluster.arrive.aligned;" ::: "memory");
    asm volatile("barrier.cluster.wait.aligned;" ::: "memory");

    if (!bottom) {
        float s = 0.0f;
        for (int g = t; g < 729; g += NT) s += R[g] * P[g];
        #pragma unroll
        for (int o = 16; o; o >>= 1) s += __shfl_xor_sync(0xFFFFFFFFu, s, o);
        if ((t & 31) == 0) red[t >> 5] = s;
        __syncthreads();
        if (t == 0) {
            float tt = 0.0f;
            #pragma unroll
            for (int w = 0; w < 8; ++w) tt += red[w];
            out[b] = tt;
        }
    }
}

extern "C" void kernel_launch(void* const* d_in, const int* in_sizes, int n_in,
                              void* d_out, int out_size) {
    const int*   xcfg = nullptr;
    const float* T    = nullptr;
    for (int i = 0; i < n_in; ++i) {
        if (in_sizes[i] == 576) xcfg = (const int*)d_in[i];
        else                    T    = (const float*)d_in[i];
    }
    float* out = (float*)d_out;
    peps_fused_kernel<<<32, NT>>>(xcfg, T, out);
}